// round 11
// baseline (speedup 1.0000x reference)
#include <cuda_runtime.h>
#include <cuda_fp16.h>
#include <cstdint>
#include <math.h>

#define NB   8
#define CCH  512
#define TT   8
#define KC   8
#define SS   4
#define HW   1024
#define EPSV 1e-5f

// ---- scratch (device globals; no allocations allowed) ----
__device__ __align__(16) __half g_zh[(size_t)NB*CCH*TT*HW];  // 64 MB
__device__ __align__(16) __half g_w2f[CCH*CCH];
__device__ float g_rp[NB*KC*TT*SS];
__device__ int   g_cp[NB*KC*TT*SS];
__device__ float g_tsum[NB*TT*4*KC];
__device__ float g_p[NB*KC*TT*SS*SS];
__device__ float g_q[NB*KC*TT*SS*SS];
__device__ float g_tm[NB*KC*2*2];

// ================= PTX helpers =================
__device__ __forceinline__ uint32_t smem_u32(const void* p) {
    uint32_t a;
    asm("{ .reg .u64 t; cvta.to.shared.u64 t, %1; cvt.u32.u64 %0, t; }" : "=r"(a) : "l"(p));
    return a;
}
#define CP16(dst, src) \
    asm volatile("cp.async.cg.shared.global [%0], [%1], 16;" :: "r"(dst), "l"(src))
#define CP_COMMIT() asm volatile("cp.async.commit_group;" ::: "memory")
#define CP_WAIT2()  asm volatile("cp.async.wait_group 2;" ::: "memory")
#define CP_WAIT1()  asm volatile("cp.async.wait_group 1;" ::: "memory")
#define CP_WAIT0()  asm volatile("cp.async.wait_group 0;" ::: "memory")

#define LDSM_X4(r, addr) \
    asm volatile("ldmatrix.sync.aligned.m8n8.x4.shared.b16 {%0,%1,%2,%3}, [%4];" \
        : "=r"((r)[0]), "=r"((r)[1]), "=r"((r)[2]), "=r"((r)[3]) : "r"(addr))
#define LDSM_X4T(r, addr) \
    asm volatile("ldmatrix.sync.aligned.m8n8.x4.trans.shared.b16 {%0,%1,%2,%3}, [%4];" \
        : "=r"((r)[0]), "=r"((r)[1]), "=r"((r)[2]), "=r"((r)[3]) : "r"(addr))

__device__ __forceinline__ void mma_f16(float* c, const uint32_t* a, const uint32_t* b) {
    asm volatile("mma.sync.aligned.m16n8k16.row.col.f32.f16.f16.f32 "
        "{%0,%1,%2,%3}, {%4,%5,%6,%7}, {%8,%9}, {%0,%1,%2,%3};"
        : "+f"(c[0]), "+f"(c[1]), "+f"(c[2]), "+f"(c[3])
        : "r"(a[0]), "r"(a[1]), "r"(a[2]), "r"(a[3]), "r"(b[0]), "r"(b[1]));
}

// ============================================================
// Kernel A: conv1 + BN1 + ReLU fused into pool reductions.
// 256 blocks, 512 threads = (cgrp in 8) x (pos in 64), unroll 4.
// Also folds w2 -> fp16 conversion.
// ============================================================
__global__ void kA(const float* __restrict__ x, const float* __restrict__ w1,
                   const float* __restrict__ b1, const float* __restrict__ g1,
                   const float* __restrict__ be1, const float* __restrict__ m1,
                   const float* __restrict__ v1, const float* __restrict__ w2)
{
    extern __shared__ float dsm[];
    float* ws  = dsm;               // 4096 floats
    float* red = dsm + 4096;        // 16384 floats
    __shared__ int   s_rp[KC];
    __shared__ int   s_cp[KC][SS];
    __shared__ float s_sum[KC];
    int tid = threadIdx.x;
    int bid = blockIdx.x;
    int sr = bid & 3, t = (bid >> 2) & 7, n = bid >> 5;

    {
        int gid = bid*512 + tid;
        float2 wv = __ldg((const float2*)w2 + gid);
        ((__half2*)g_w2f)[gid] = __floats2half2_rn(wv.x, wv.y);
    }

    for (int i = tid; i < CCH*KC; i += 512) {
        int c = i >> 3, k = i & 7;
        ws[i] = w1[k*CCH + c];
    }
    if (tid < KC) { s_rp[tid] = 0; s_sum[tid] = 0.f; }
    if (tid < KC*SS) s_cp[tid >> 2][tid & 3] = 0;
    __syncthreads();

    int pos = tid & 63, cgrp = tid >> 6;
    int r = pos >> 3, wseg = pos & 7;
    const float4* xb = (const float4*)(x + (size_t)n*CCH*TT*HW
                        + (size_t)cgrp*64*TT*HW + (size_t)t*HW
                        + (size_t)(sr*8 + r)*32) + wseg;

    float acc[KC][4];
#pragma unroll
    for (int k = 0; k < KC; k++)
#pragma unroll
        for (int j = 0; j < 4; j++) acc[k][j] = 0.f;

#pragma unroll 4
    for (int c = 0; c < 64; c++) {
        float4 xv = __ldg(xb + (size_t)c*(TT*HW/4));
        const float4* wp = (const float4*)&ws[(cgrp*64 + c)*8];
        float4 wa = wp[0], wb = wp[1];
        float wk[8] = {wa.x, wa.y, wa.z, wa.w, wb.x, wb.y, wb.z, wb.w};
#pragma unroll
        for (int k = 0; k < KC; k++) {
            acc[k][0] += wk[k]*xv.x; acc[k][1] += wk[k]*xv.y;
            acc[k][2] += wk[k]*xv.z; acc[k][3] += wk[k]*xv.w;
        }
    }

#pragma unroll
    for (int k = 0; k < KC; k++)
#pragma unroll
        for (int j = 0; j < 4; j++)
            red[((j*8 + k)*8 + cgrp)*64 + pos] = acc[k][j];
    __syncthreads();

    if (tid < 64) {
        int lane = tid & 31;
#pragma unroll
        for (int k = 0; k < KC; k++) {
            float sc = __ldg(g1 + k) * rsqrtf(__ldg(v1 + k) + EPSV);
            float bb = (__ldg(b1 + k) - __ldg(m1 + k)) * sc + __ldg(be1 + k);
            float vj[4];
#pragma unroll
            for (int j = 0; j < 4; j++) {
                float s = 0.f;
#pragma unroll
                for (int g = 0; g < 8; g++)
                    s += red[((j*8 + k)*8 + g)*64 + pos];
                vj[j] = fmaxf(s*sc + bb, 0.f);
            }
            float m4 = fmaxf(fmaxf(vj[0], vj[1]), fmaxf(vj[2], vj[3]));
            float sm = vj[0] + vj[1] + vj[2] + vj[3];
            float bm = m4;
#pragma unroll
            for (int d = 16; d; d >>= 1) bm = fmaxf(bm, __shfl_xor_sync(0xffffffffu, bm, d));
            float cm = fmaxf(m4, __shfl_xor_sync(0xffffffffu, m4, 1));
            cm = fmaxf(cm, __shfl_xor_sync(0xffffffffu, cm, 8));
            cm = fmaxf(cm, __shfl_xor_sync(0xffffffffu, cm, 16));
#pragma unroll
            for (int d = 16; d; d >>= 1) sm += __shfl_xor_sync(0xffffffffu, sm, d);
            if (lane == 0) {
                atomicMax(&s_rp[k], __float_as_int(bm));
                atomicAdd(&s_sum[k], sm);
            }
            if (lane < 8 && (lane & 1) == 0)
                atomicMax(&s_cp[k][lane >> 1], __float_as_int(cm));
        }
    }
    __syncthreads();

    if (tid < KC) {
        g_rp[((n*KC + tid)*TT + t)*SS + sr]  = __int_as_float(s_rp[tid]);
        g_tsum[((n*TT + t)*4 + sr)*KC + tid] = s_sum[tid];
    }
    if (tid < KC*SS) {
        int k = tid >> 2, sc = tid & 3;
        atomicMax(&g_cp[((n*KC + k)*TT + t)*SS + sc], s_cp[k][sc]);
    }
}

// ============================================================
// Kernel B: conv_p / conv_q / conv_t + softmaxes.
// ============================================================
__global__ void kB(const float* __restrict__ wp, const float* __restrict__ bp,
                   const float* __restrict__ wq, const float* __restrict__ bq,
                   const float* __restrict__ wt, const float* __restrict__ bt)
{
    int g = blockIdx.x * 256 + threadIdx.x;
    {
        int n = g >> 8;
        int rr = g & 255;
        int k = rr >> 5;
        int a = (rr >> 3) & 3;
        int t = rr & 7;
        float vp[4], vq[4];
#pragma unroll
        for (int b = 0; b < 4; b++) {
            vp[b] = __ldg(bp + (k*16 + a*4 + b));
            vq[b] = __ldg(bq + (k*16 + b*4 + a));
        }
        for (int c = 0; c < 8; c++) {
#pragma unroll
            for (int i = 0; i < 4; i++) {
                float rv = g_rp[((n*8 + c)*8 + t)*4 + i];
                float cv = __int_as_float(g_cp[((n*8 + c)*8 + t)*4 + i]);
#pragma unroll
                for (int b = 0; b < 4; b++) {
                    vp[b] += __ldg(wp + (size_t)(k*16 + a*4 + b)*32 + c*4 + i) * rv;
                    vq[b] += __ldg(wq + (size_t)(k*16 + b*4 + a)*32 + c*4 + i) * cv;
                }
            }
        }
        float m = vp[0], e[4], s = 0.f;
        for (int b = 1; b < 4; b++) m = fmaxf(m, vp[b]);
        for (int b = 0; b < 4; b++) { e[b] = expf(vp[b] - m); s += e[b]; }
        float inv = 1.f / s;
        for (int b = 0; b < 4; b++) g_p[((n*8 + k)*8 + t)*16 + a*4 + b] = e[b] * inv;
        m = vq[0]; s = 0.f;
        for (int b = 1; b < 4; b++) m = fmaxf(m, vq[b]);
        for (int b = 0; b < 4; b++) { e[b] = expf(vq[b] - m); s += e[b]; }
        inv = 1.f / s;
        for (int b = 0; b < 4; b++) g_q[((n*8 + k)*8 + t)*16 + b*4 + a] = e[b] * inv;
    }
    if (g < 128) {
        int n = g >> 4, tk = (g >> 1) & 7, A = g & 1;
        float tp[8][2];
        for (int c = 0; c < 8; c++)
            for (int i = 0; i < 2; i++) {
                float sum = 0.f;
                for (int t2 = 0; t2 < 4; t2++)
                    for (int srx = 0; srx < 4; srx++)
                        sum += g_tsum[((n*8 + (i*4 + t2))*4 + srx)*8 + c];
                tp[c][i] = sum * (1.f / 4096.f);
            }
        int o0 = tk*4 + A*2;
        float v0 = __ldg(bt + o0), v1 = __ldg(bt + o0 + 1);
        for (int c = 0; c < 8; c++)
            for (int i = 0; i < 2; i++) {
                v0 += __ldg(wt + (size_t)o0*16 + c*2 + i) * tp[c][i];
                v1 += __ldg(wt + (size_t)(o0 + 1)*16 + c*2 + i) * tp[c][i];
            }
        float m2 = fmaxf(v0, v1);
        float e0 = expf(v0 - m2), e1 = expf(v1 - m2);
        float inv2 = 1.f / (e0 + e1);
        g_tm[((n*8 + tk)*2 + A)*2 + 0] = e0 * inv2;
        g_tm[((n*8 + tk)*2 + A)*2 + 1] = e1 * inv2;
    }
}

// ============================================================
// Kernel C: spatial + temporal mixing -> z (fp16), 2 channels/block.
// ============================================================
__global__ void kC(const float* __restrict__ x)
{
    __shared__ float4 sx4[4*256];
    __shared__ float ysm[2][32*33];
    __shared__ float sP[2][16], sQ[2][16], sTM[4];
    int tid = threadIdx.x;
    int bid = blockIdx.x;
    int u = bid & 3;
    int cpair = (bid >> 2) & 255;
    int n = bid >> 10;
    int base = cpair & 31, grp = cpair >> 5;
    int c0 = grp*64 + base, c1 = c0 + 32, k = grp;

    if (tid < 16) {
        int b0 = ((n*8 + k)*8 + u)*16;
        int b1 = ((n*8 + k)*8 + u + 4)*16;
        sP[0][tid] = g_p[b0 + tid]; sP[1][tid] = g_p[b1 + tid];
        sQ[0][tid] = g_q[b0 + tid]; sQ[1][tid] = g_q[b1 + tid];
    }
    if (tid < 4) sTM[tid] = g_tm[(n*8 + k)*4 + tid];

    const float4* xb0 = (const float4*)(x + (size_t)(n*CCH + c0)*TT*HW);
    const float4* xb1 = (const float4*)(x + (size_t)(n*CCH + c1)*TT*HW);
    sx4[tid]       = __ldg(xb0 + (size_t)u*256 + tid);
    sx4[256 + tid] = __ldg(xb0 + (size_t)(u + 4)*256 + tid);
    sx4[512 + tid] = __ldg(xb1 + (size_t)u*256 + tid);
    sx4[768 + tid] = __ldg(xb1 + (size_t)(u + 4)*256 + tid);
    __syncthreads();

    int h = tid >> 3, tw = tid & 7;
    int a = h >> 3, hr = h & 7;
    float o0[2][4] = {{0,0,0,0},{0,0,0,0}};
    float o1[2][4] = {{0,0,0,0},{0,0,0,0}};

#pragma unroll
    for (int j = 0; j < 2; j++) {
        float4 y1[2];
#pragma unroll
        for (int ch = 0; ch < 2; ch++) {
            y1[ch] = make_float4(0,0,0,0);
#pragma unroll
            for (int b = 0; b < 4; b++) {
                float pw = sP[j][a*4 + b];
                float4 xv = sx4[(ch*2 + j)*256 + (b*8 + hr)*8 + tw];
                y1[ch].x += pw*xv.x; y1[ch].y += pw*xv.y;
                y1[ch].z += pw*xv.z; y1[ch].w += pw*xv.w;
            }
        }
        __syncthreads();
#pragma unroll
        for (int ch = 0; ch < 2; ch++) {
            ysm[ch][h*33 + tw*4 + 0] = y1[ch].x;
            ysm[ch][h*33 + tw*4 + 1] = y1[ch].y;
            ysm[ch][h*33 + tw*4 + 2] = y1[ch].z;
            ysm[ch][h*33 + tw*4 + 3] = y1[ch].w;
        }
        __syncthreads();
        int bcol = tw >> 1;
        float tm0 = sTM[0*2 + j], tm1 = sTM[1*2 + j];
#pragma unroll
        for (int ch = 0; ch < 2; ch++) {
#pragma unroll
            for (int i2 = 0; i2 < 4; i2++) {
                int v = (tw & 1)*4 + i2;
                float y2 = 0.f;
#pragma unroll
                for (int aa = 0; aa < 4; aa++)
                    y2 += ysm[ch][h*33 + aa*8 + v] * sQ[j][aa*4 + bcol];
                o0[ch][i2] += tm0 * y2;
                o1[ch][i2] += tm1 * y2;
            }
        }
    }

#pragma unroll
    for (int ch = 0; ch < 2; ch++) {
        int c = ch ? c1 : c0;
        size_t bofs = (size_t)(n*CCH + c)*TT*HW + h*32 + tw*4;
#pragma unroll
        for (int pl = 0; pl < 2; pl++) {
            float* vv = pl ? o1[ch] : o0[ch];
            size_t off = bofs + (size_t)(u + pl*4)*HW;
            *(__half2*)(g_zh + off)     = __floats2half2_rn(vv[0], vv[1]);
            *(__half2*)(g_zh + off + 2) = __floats2half2_rn(vv[2], vv[3]);
        }
    }
}

// ============================================================
// Kernel D: conv2 via mma.sync fp16 + BN2 + ReLU.
// CTA = 128(M) x 128(N), K=512 in 16 chunks of 32 (halved barriers).
// 4-stage cp.async ring (dynamic smem, 75.8 KB), reg double-buffered B.
// Stage: A[128 rows x 32k] 80B-padded rows (10240 B) +
//        B[32 k-rows x 272B] (8704 B) = 18944 B.
// ============================================================
#define STAGE_BYTES 18944
#define SB_B  10240
#define NSTAGE 4

__global__ void __launch_bounds__(256) kD(
        const float* __restrict__ b2, const float* __restrict__ g2,
        const float* __restrict__ be2, const float* __restrict__ m2,
        const float* __restrict__ v2, float* __restrict__ out)
{
    extern __shared__ __align__(128) uint8_t smem[];
    uint32_t smb = smem_u32(smem);
    int tid = threadIdx.x;
    int wid = tid >> 5, lane = tid & 31;

    int mtile = blockIdx.x & 3;
    int ptile = (blockIdx.x >> 2) & 63;
    int n = blockIdx.x >> 8;
    int pbase = ptile * 128;

    const __half* zh = g_zh + (size_t)n*CCH*TT*HW;

    // cp.async indices (2 A + 2 B CP16 per thread per stage)
    int a_row = tid >> 1;                       // with q: idx=tid*2+q -> row=idx>>2, seg=idx&3
    int b_rowseg = tid;                          // idx=tid*2+q -> row=idx>>4, seg=idx&15
    (void)a_row; (void)b_rowseg;

#define ISSUE(kk, st) do { \
        uint32_t sb_ = smb + (st)*STAGE_BYTES; \
        _Pragma("unroll") \
        for (int q = 0; q < 2; q++) { \
            int ia = tid*2 + q; \
            int ar = ia >> 2, as = ia & 3; \
            CP16(sb_ + ar*80 + as*16, \
                 g_w2f + (size_t)(mtile*128 + ar)*CCH + (kk) + as*8); \
            int br = ia >> 4, bs = ia & 15; \
            CP16(sb_ + SB_B + br*272 + bs*16, \
                 zh + (size_t)((kk) + br)*TT*HW + pbase + bs*8); \
        } \
    } while (0)

    float acc[2][8][4];
#pragma unroll
    for (int i = 0; i < 2; i++)
#pragma unroll
        for (int j = 0; j < 8; j++)
#pragma unroll
            for (int l = 0; l < 4; l++) acc[i][j][l] = 0.f;

    int wm = (wid & 3) * 32;
    int wn = wid >> 2;

    int lrow = (lane & 7) + ((lane >> 3) & 1) * 8;   // 0..15
    int aseg = (lane >> 4) & 1;
    uint32_t a_lm = (wm + lrow) * 80 + aseg * 16;     // + ks*32
    uint32_t b_col = (wn*64 + aseg * 8) * 2;          // byte offset in B row
    uint32_t b_lm = SB_B + lrow * 272 + b_col;        // + ks*16*272

    ISSUE(0, 0);  CP_COMMIT();
    ISSUE(32, 1); CP_COMMIT();
    ISSUE(64, 2); CP_COMMIT();

#pragma unroll 2
    for (int i = 0; i < 16; i++) {
        if (i <= 13) { CP_WAIT2(); }
        else if (i == 14) { CP_WAIT1(); }
        else { CP_WAIT0(); }
        __syncthreads();

        uint32_t sb = smb + (i & (NSTAGE - 1))*STAGE_BYTES;

        if (i <= 12) {
            ISSUE((i + 3) * 32, (i + 3) & (NSTAGE - 1));
            CP_COMMIT();
        }

#pragma unroll
        for (int ks = 0; ks < 2; ks++) {
            uint32_t aF[2][4];
            uint32_t bh[2][4];
            LDSM_X4(aF[0], sb + a_lm + ks*32);
            LDSM_X4(aF[1], sb + a_lm + ks*32 + 16*80);
            LDSM_X4T(bh[0], sb + b_lm + ks*16*272);
#pragma unroll
            for (int g = 0; g < 4; g++) {
                if (g < 3) LDSM_X4T(bh[(g + 1) & 1], sb + b_lm + ks*16*272 + (g + 1)*32);
                const uint32_t* bc = bh[g & 1];
                mma_f16(acc[0][2*g],   aF[0], bc);
                mma_f16(acc[0][2*g+1], aF[0], bc + 2);
                mma_f16(acc[1][2*g],   aF[1], bc);
                mma_f16(acc[1][2*g+1], aF[1], bc + 2);
            }
        }
    }

#pragma unroll
    for (int mt = 0; mt < 2; mt++) {
        int r0 = wm + mt*16 + (lane >> 2);
#pragma unroll
        for (int hf = 0; hf < 2; hf++) {
            int o = mtile*128 + r0 + hf*8;
            float sc = __ldg(g2 + o) * rsqrtf(__ldg(v2 + o) + EPSV);
            float bb = (__ldg(b2 + o) - __ldg(m2 + o)) * sc + __ldg(be2 + o);
            float* op = out + ((size_t)n*CCH + o)*TT*HW + pbase + wn*64 + (lane & 3)*2;
#pragma unroll
            for (int nt = 0; nt < 8; nt++) {
                float2 v;
                v.x = fmaxf(acc[mt][nt][hf*2 + 0]*sc + bb, 0.f);
                v.y = fmaxf(acc[mt][nt][hf*2 + 1]*sc + bb, 0.f);
                *(float2*)(op + nt*8) = v;
            }
        }
    }
#undef ISSUE
}

extern "C" void kernel_launch(void* const* d_in, const int* in_sizes, int n_in,
                              void* d_out, int out_size)
{
    (void)in_sizes; (void)n_in; (void)out_size;
    const float* x   = (const float*)d_in[0];
    const float* w1  = (const float*)d_in[1];
    const float* b1  = (const float*)d_in[2];
    const float* g1  = (const float*)d_in[3];
    const float* be1 = (const float*)d_in[4];
    const float* m1  = (const float*)d_in[5];
    const float* v1  = (const float*)d_in[6];
    const float* wp  = (const float*)d_in[7];
    const float* bp  = (const float*)d_in[8];
    const float* wq  = (const float*)d_in[9];
    const float* bq  = (const float*)d_in[10];
    const float* wt  = (const float*)d_in[11];
    const float* bt  = (const float*)d_in[12];
    const float* w2  = (const float*)d_in[13];
    const float* b2  = (const float*)d_in[14];
    const float* g2  = (const float*)d_in[15];
    const float* be2 = (const float*)d_in[16];
    const float* m2  = (const float*)d_in[17];
    const float* v2  = (const float*)d_in[18];
    float* out = (float*)d_out;

    const int kA_smem = (4096 + 16384) * 4;          // 80 KB
    cudaFuncSetAttribute(kA, cudaFuncAttributeMaxDynamicSharedMemorySize, kA_smem);
    const int kD_smem = NSTAGE * STAGE_BYTES;        // 75776 B
    cudaFuncSetAttribute(kD, cudaFuncAttributeMaxDynamicSharedMemorySize, kD_smem);

    kA<<<256, 512, kA_smem>>>(x, w1, b1, g1, be1, m1, v1, w2);
    kB<<<8, 256>>>(wp, bp, wq, bq, wt, bt);
    kC<<<NB*256*4, 256>>>(x);
    kD<<<2048, 256, kD_smem>>>(b2, g2, be2, m2, v2, out);
}

// round 12
// speedup vs baseline: 1.0908x; 1.0908x over previous
#include <cuda_runtime.h>
#include <cuda_fp16.h>
#include <cstdint>
#include <math.h>

#define NB   8
#define CCH  512
#define TT   8
#define KC   8
#define SS   4
#define HW   1024
#define EPSV 1e-5f

// ---- scratch (device globals; no allocations allowed) ----
__device__ __align__(16) __half g_zh[(size_t)NB*CCH*TT*HW];  // 64 MB
__device__ __align__(16) __half g_w2f[CCH*CCH];
__device__ float g_rp[NB*KC*TT*SS];
__device__ int   g_cp[NB*KC*TT*SS];
__device__ float g_tsum[NB*TT*4*KC];
__device__ float g_p[NB*KC*TT*SS*SS];
__device__ float g_q[NB*KC*TT*SS*SS];
__device__ float g_tm[NB*KC*2*2];

// ================= PTX helpers =================
__device__ __forceinline__ uint32_t smem_u32(const void* p) {
    uint32_t a;
    asm("{ .reg .u64 t; cvta.to.shared.u64 t, %1; cvt.u32.u64 %0, t; }" : "=r"(a) : "l"(p));
    return a;
}
#define CP16(dst, src) \
    asm volatile("cp.async.cg.shared.global [%0], [%1], 16;" :: "r"(dst), "l"(src))
#define CP_COMMIT() asm volatile("cp.async.commit_group;" ::: "memory")
#define CP_WAIT2()  asm volatile("cp.async.wait_group 2;" ::: "memory")
#define CP_WAIT1()  asm volatile("cp.async.wait_group 1;" ::: "memory")
#define CP_WAIT0()  asm volatile("cp.async.wait_group 0;" ::: "memory")

#define LDSM_X4(r, addr) \
    asm volatile("ldmatrix.sync.aligned.m8n8.x4.shared.b16 {%0,%1,%2,%3}, [%4];" \
        : "=r"((r)[0]), "=r"((r)[1]), "=r"((r)[2]), "=r"((r)[3]) : "r"(addr))
#define LDSM_X4T(r, addr) \
    asm volatile("ldmatrix.sync.aligned.m8n8.x4.trans.shared.b16 {%0,%1,%2,%3}, [%4];" \
        : "=r"((r)[0]), "=r"((r)[1]), "=r"((r)[2]), "=r"((r)[3]) : "r"(addr))

__device__ __forceinline__ void mma_f16(float* c, const uint32_t* a, const uint32_t* b) {
    asm volatile("mma.sync.aligned.m16n8k16.row.col.f32.f16.f16.f32 "
        "{%0,%1,%2,%3}, {%4,%5,%6,%7}, {%8,%9}, {%0,%1,%2,%3};"
        : "+f"(c[0]), "+f"(c[1]), "+f"(c[2]), "+f"(c[3])
        : "r"(a[0]), "r"(a[1]), "r"(a[2]), "r"(a[3]), "r"(b[0]), "r"(b[1]));
}

// ============================================================
// Kernel A: conv1 + BN1 + ReLU fused into pool reductions.
// 256 blocks, 512 threads = (cgrp in 8) x (pos in 64), unroll 4.
// Also folds w2 -> fp16 conversion.
// ============================================================
__global__ void kA(const float* __restrict__ x, const float* __restrict__ w1,
                   const float* __restrict__ b1, const float* __restrict__ g1,
                   const float* __restrict__ be1, const float* __restrict__ m1,
                   const float* __restrict__ v1, const float* __restrict__ w2)
{
    extern __shared__ float dsm[];
    float* ws  = dsm;               // 4096 floats
    float* red = dsm + 4096;        // 16384 floats
    __shared__ int   s_rp[KC];
    __shared__ int   s_cp[KC][SS];
    __shared__ float s_sum[KC];
    int tid = threadIdx.x;
    int bid = blockIdx.x;
    int sr = bid & 3, t = (bid >> 2) & 7, n = bid >> 5;

    {
        int gid = bid*512 + tid;
        float2 wv = __ldg((const float2*)w2 + gid);
        ((__half2*)g_w2f)[gid] = __floats2half2_rn(wv.x, wv.y);
    }

    for (int i = tid; i < CCH*KC; i += 512) {
        int c = i >> 3, k = i & 7;
        ws[i] = w1[k*CCH + c];
    }
    if (tid < KC) { s_rp[tid] = 0; s_sum[tid] = 0.f; }
    if (tid < KC*SS) s_cp[tid >> 2][tid & 3] = 0;
    __syncthreads();

    int pos = tid & 63, cgrp = tid >> 6;
    int r = pos >> 3, wseg = pos & 7;
    const float4* xb = (const float4*)(x + (size_t)n*CCH*TT*HW
                        + (size_t)cgrp*64*TT*HW + (size_t)t*HW
                        + (size_t)(sr*8 + r)*32) + wseg;

    float acc[KC][4];
#pragma unroll
    for (int k = 0; k < KC; k++)
#pragma unroll
        for (int j = 0; j < 4; j++) acc[k][j] = 0.f;

#pragma unroll 4
    for (int c = 0; c < 64; c++) {
        float4 xv = __ldg(xb + (size_t)c*(TT*HW/4));
        const float4* wp = (const float4*)&ws[(cgrp*64 + c)*8];
        float4 wa = wp[0], wb = wp[1];
        float wk[8] = {wa.x, wa.y, wa.z, wa.w, wb.x, wb.y, wb.z, wb.w};
#pragma unroll
        for (int k = 0; k < KC; k++) {
            acc[k][0] += wk[k]*xv.x; acc[k][1] += wk[k]*xv.y;
            acc[k][2] += wk[k]*xv.z; acc[k][3] += wk[k]*xv.w;
        }
    }

#pragma unroll
    for (int k = 0; k < KC; k++)
#pragma unroll
        for (int j = 0; j < 4; j++)
            red[((j*8 + k)*8 + cgrp)*64 + pos] = acc[k][j];
    __syncthreads();

    if (tid < 64) {
        int lane = tid & 31;
#pragma unroll
        for (int k = 0; k < KC; k++) {
            float sc = __ldg(g1 + k) * rsqrtf(__ldg(v1 + k) + EPSV);
            float bb = (__ldg(b1 + k) - __ldg(m1 + k)) * sc + __ldg(be1 + k);
            float vj[4];
#pragma unroll
            for (int j = 0; j < 4; j++) {
                float s = 0.f;
#pragma unroll
                for (int g = 0; g < 8; g++)
                    s += red[((j*8 + k)*8 + g)*64 + pos];
                vj[j] = fmaxf(s*sc + bb, 0.f);
            }
            float m4 = fmaxf(fmaxf(vj[0], vj[1]), fmaxf(vj[2], vj[3]));
            float sm = vj[0] + vj[1] + vj[2] + vj[3];
            float bm = m4;
#pragma unroll
            for (int d = 16; d; d >>= 1) bm = fmaxf(bm, __shfl_xor_sync(0xffffffffu, bm, d));
            float cm = fmaxf(m4, __shfl_xor_sync(0xffffffffu, m4, 1));
            cm = fmaxf(cm, __shfl_xor_sync(0xffffffffu, cm, 8));
            cm = fmaxf(cm, __shfl_xor_sync(0xffffffffu, cm, 16));
#pragma unroll
            for (int d = 16; d; d >>= 1) sm += __shfl_xor_sync(0xffffffffu, sm, d);
            if (lane == 0) {
                atomicMax(&s_rp[k], __float_as_int(bm));
                atomicAdd(&s_sum[k], sm);
            }
            if (lane < 8 && (lane & 1) == 0)
                atomicMax(&s_cp[k][lane >> 1], __float_as_int(cm));
        }
    }
    __syncthreads();

    if (tid < KC) {
        g_rp[((n*KC + tid)*TT + t)*SS + sr]  = __int_as_float(s_rp[tid]);
        g_tsum[((n*TT + t)*4 + sr)*KC + tid] = s_sum[tid];
    }
    if (tid < KC*SS) {
        int k = tid >> 2, sc = tid & 3;
        atomicMax(&g_cp[((n*KC + k)*TT + t)*SS + sc], s_cp[k][sc]);
    }
}

// ============================================================
// Kernel B: conv_p / conv_q / conv_t + softmaxes.
// ============================================================
__global__ void kB(const float* __restrict__ wp, const float* __restrict__ bp,
                   const float* __restrict__ wq, const float* __restrict__ bq,
                   const float* __restrict__ wt, const float* __restrict__ bt)
{
    int g = blockIdx.x * 256 + threadIdx.x;
    {
        int n = g >> 8;
        int rr = g & 255;
        int k = rr >> 5;
        int a = (rr >> 3) & 3;
        int t = rr & 7;
        float vp[4], vq[4];
#pragma unroll
        for (int b = 0; b < 4; b++) {
            vp[b] = __ldg(bp + (k*16 + a*4 + b));
            vq[b] = __ldg(bq + (k*16 + b*4 + a));
        }
        for (int c = 0; c < 8; c++) {
#pragma unroll
            for (int i = 0; i < 4; i++) {
                float rv = g_rp[((n*8 + c)*8 + t)*4 + i];
                float cv = __int_as_float(g_cp[((n*8 + c)*8 + t)*4 + i]);
#pragma unroll
                for (int b = 0; b < 4; b++) {
                    vp[b] += __ldg(wp + (size_t)(k*16 + a*4 + b)*32 + c*4 + i) * rv;
                    vq[b] += __ldg(wq + (size_t)(k*16 + b*4 + a)*32 + c*4 + i) * cv;
                }
            }
        }
        float m = vp[0], e[4], s = 0.f;
        for (int b = 1; b < 4; b++) m = fmaxf(m, vp[b]);
        for (int b = 0; b < 4; b++) { e[b] = expf(vp[b] - m); s += e[b]; }
        float inv = 1.f / s;
        for (int b = 0; b < 4; b++) g_p[((n*8 + k)*8 + t)*16 + a*4 + b] = e[b] * inv;
        m = vq[0]; s = 0.f;
        for (int b = 1; b < 4; b++) m = fmaxf(m, vq[b]);
        for (int b = 0; b < 4; b++) { e[b] = expf(vq[b] - m); s += e[b]; }
        inv = 1.f / s;
        for (int b = 0; b < 4; b++) g_q[((n*8 + k)*8 + t)*16 + b*4 + a] = e[b] * inv;
    }
    if (g < 128) {
        int n = g >> 4, tk = (g >> 1) & 7, A = g & 1;
        float tp[8][2];
        for (int c = 0; c < 8; c++)
            for (int i = 0; i < 2; i++) {
                float sum = 0.f;
                for (int t2 = 0; t2 < 4; t2++)
                    for (int srx = 0; srx < 4; srx++)
                        sum += g_tsum[((n*8 + (i*4 + t2))*4 + srx)*8 + c];
                tp[c][i] = sum * (1.f / 4096.f);
            }
        int o0 = tk*4 + A*2;
        float v0 = __ldg(bt + o0), v1 = __ldg(bt + o0 + 1);
        for (int c = 0; c < 8; c++)
            for (int i = 0; i < 2; i++) {
                v0 += __ldg(wt + (size_t)o0*16 + c*2 + i) * tp[c][i];
                v1 += __ldg(wt + (size_t)(o0 + 1)*16 + c*2 + i) * tp[c][i];
            }
        float m2 = fmaxf(v0, v1);
        float e0 = expf(v0 - m2), e1 = expf(v1 - m2);
        float inv2 = 1.f / (e0 + e1);
        g_tm[((n*8 + tk)*2 + A)*2 + 0] = e0 * inv2;
        g_tm[((n*8 + tk)*2 + A)*2 + 1] = e1 * inv2;
    }
}

// ============================================================
// Kernel C: spatial + temporal mixing -> z (fp16), 2 channels/block.
// Phase-2 (Q mix) via warp shuffles — ONE __syncthreads total.
// ============================================================
__global__ void kC(const float* __restrict__ x)
{
    __shared__ float4 sx4[4*256];
    __shared__ float sP[2][16], sQ[2][16], sTM[4];
    int tid = threadIdx.x;
    int bid = blockIdx.x;
    int u = bid & 3;
    int cpair = (bid >> 2) & 255;
    int n = bid >> 10;
    int base = cpair & 31, grp = cpair >> 5;
    int c0 = grp*64 + base, c1 = c0 + 32, k = grp;

    if (tid < 16) {
        int b0 = ((n*8 + k)*8 + u)*16;
        int b1 = ((n*8 + k)*8 + u + 4)*16;
        sP[0][tid] = g_p[b0 + tid]; sP[1][tid] = g_p[b1 + tid];
        sQ[0][tid] = g_q[b0 + tid]; sQ[1][tid] = g_q[b1 + tid];
    }
    if (tid < 4) sTM[tid] = g_tm[(n*8 + k)*4 + tid];

    const float4* xb0 = (const float4*)(x + (size_t)(n*CCH + c0)*TT*HW);
    const float4* xb1 = (const float4*)(x + (size_t)(n*CCH + c1)*TT*HW);
    sx4[tid]       = __ldg(xb0 + (size_t)u*256 + tid);
    sx4[256 + tid] = __ldg(xb0 + (size_t)(u + 4)*256 + tid);
    sx4[512 + tid] = __ldg(xb1 + (size_t)u*256 + tid);
    sx4[768 + tid] = __ldg(xb1 + (size_t)(u + 4)*256 + tid);
    __syncthreads();

    int lane = tid & 31;
    int h = tid >> 3, tw = tid & 7;
    int a = h >> 3, hr = h & 7;
    int bcol = tw >> 1;
    int srcbase = (lane & 24) | (lane & 1);     // + aa*2
    float o0[2][4] = {{0,0,0,0},{0,0,0,0}};
    float o1[2][4] = {{0,0,0,0},{0,0,0,0}};

#pragma unroll
    for (int j = 0; j < 2; j++) {
        float tm0 = sTM[0*2 + j], tm1 = sTM[1*2 + j];
#pragma unroll
        for (int ch = 0; ch < 2; ch++) {
            // phase 1: row-block mix (P)
            float4 y1 = make_float4(0,0,0,0);
#pragma unroll
            for (int b = 0; b < 4; b++) {
                float pw = sP[j][a*4 + b];
                float4 xv = sx4[(ch*2 + j)*256 + (b*8 + hr)*8 + tw];
                y1.x += pw*xv.x; y1.y += pw*xv.y; y1.z += pw*xv.z; y1.w += pw*xv.w;
            }
            // phase 2: col-block mix (Q) via shuffles within 8-lane row group
            float y2[4] = {0,0,0,0};
#pragma unroll
            for (int aa = 0; aa < 4; aa++) {
                int src = srcbase + aa*2;
                float qv = sQ[j][aa*4 + bcol];
                float sxx = __shfl_sync(0xffffffffu, y1.x, src);
                float sxy = __shfl_sync(0xffffffffu, y1.y, src);
                float sxz = __shfl_sync(0xffffffffu, y1.z, src);
                float sxw = __shfl_sync(0xffffffffu, y1.w, src);
                y2[0] += qv*sxx; y2[1] += qv*sxy; y2[2] += qv*sxz; y2[3] += qv*sxw;
            }
#pragma unroll
            for (int i2 = 0; i2 < 4; i2++) {
                o0[ch][i2] += tm0 * y2[i2];
                o1[ch][i2] += tm1 * y2[i2];
            }
        }
    }

#pragma unroll
    for (int ch = 0; ch < 2; ch++) {
        int c = ch ? c1 : c0;
        size_t bofs = (size_t)(n*CCH + c)*TT*HW + h*32 + tw*4;
#pragma unroll
        for (int pl = 0; pl < 2; pl++) {
            float* vv = pl ? o1[ch] : o0[ch];
            size_t off = bofs + (size_t)(u + pl*4)*HW;
            *(__half2*)(g_zh + off)     = __floats2half2_rn(vv[0], vv[1]);
            *(__half2*)(g_zh + off + 2) = __floats2half2_rn(vv[2], vv[3]);
        }
    }
}

// ============================================================
// Kernel D: conv2 via mma.sync fp16 + BN2 + ReLU.  (R10 version)
// CTA = 128(M) x 128(N), K=512 in 32 chunks of 16.
// 4-stage cp.async; register double-buffered ldmatrix.
// mtile in LOW bits of blockIdx.x so co-resident CTAs share B.
// ============================================================
#define STAGE_BYTES 10496
#define SB_H  6144
#define NSTAGE 4

__global__ void __launch_bounds__(256) kD(
        const float* __restrict__ b2, const float* __restrict__ g2,
        const float* __restrict__ be2, const float* __restrict__ m2,
        const float* __restrict__ v2, float* __restrict__ out)
{
    __shared__ __align__(128) uint8_t smem[NSTAGE*STAGE_BYTES];
    uint32_t smb = smem_u32(smem);
    int tid = threadIdx.x;
    int wid = tid >> 5, lane = tid & 31;

    int mtile = blockIdx.x & 3;
    int ptile = (blockIdx.x >> 2) & 63;
    int n = blockIdx.x >> 8;
    int pbase = ptile * 128;

    const __half* zh = g_zh + (size_t)n*CCH*TT*HW;

    int a_row = tid >> 1, a_seg = tid & 1;
    int b_row = tid >> 4, b_seg = tid & 15;
    size_t a_goff = (size_t)(mtile*128 + a_row)*CCH + a_seg*8;
    size_t b_goff = (size_t)b_row*TT*HW + pbase + b_seg*8;
    uint32_t a_soff = a_row*48 + a_seg*16;
    uint32_t b_soff = SB_H + b_row*272 + b_seg*16;

#define ISSUE(kk, st) do { \
        uint32_t sb_ = smb + (st)*STAGE_BYTES; \
        CP16(sb_ + a_soff, g_w2f + a_goff + (kk)); \
        CP16(sb_ + b_soff, zh + b_goff + (size_t)(kk)*TT*HW); \
    } while (0)

    float acc[2][8][4];
#pragma unroll
    for (int i = 0; i < 2; i++)
#pragma unroll
        for (int j = 0; j < 8; j++)
#pragma unroll
            for (int l = 0; l < 4; l++) acc[i][j][l] = 0.f;

    int wm = (wid & 3) * 32;
    int wn = wid >> 2;

    int lrow = (lane & 7) + ((lane >> 3) & 1) * 8;
    uint32_t a_lm = (wm + lrow) * 48 + ((lane >> 4) & 1) * 16;
    uint32_t b_lm = SB_H + lrow * 272 + (wn*64 + ((lane >> 4) & 1) * 8) * 2;

    ISSUE(0, 0);  CP_COMMIT();
    ISSUE(16, 1); CP_COMMIT();
    ISSUE(32, 2); CP_COMMIT();

#pragma unroll 4
    for (int i = 0; i < 32; i++) {
        if (i <= 29) { CP_WAIT2(); }
        else if (i == 30) { CP_WAIT1(); }
        else { CP_WAIT0(); }
        __syncthreads();

        uint32_t sb = smb + (i & (NSTAGE - 1))*STAGE_BYTES;
        uint32_t aF[2][4];
        uint32_t bh[2][4];
        LDSM_X4(aF[0], sb + a_lm);
        LDSM_X4(aF[1], sb + a_lm + 16*48);
        LDSM_X4T(bh[0], sb + b_lm);

        if (i <= 28) {
            ISSUE((i + 3) * 16, (i + 3) & (NSTAGE - 1));
            CP_COMMIT();
        }

#pragma unroll
        for (int g = 0; g < 4; g++) {
            if (g < 3) LDSM_X4T(bh[(g + 1) & 1], sb + b_lm + (g + 1)*32);
            const uint32_t* bc = bh[g & 1];
            mma_f16(acc[0][2*g],   aF[0], bc);
            mma_f16(acc[0][2*g+1], aF[0], bc + 2);
            mma_f16(acc[1][2*g],   aF[1], bc);
            mma_f16(acc[1][2*g+1], aF[1], bc + 2);
        }
    }

#pragma unroll
    for (int mt = 0; mt < 2; mt++) {
        int r0 = wm + mt*16 + (lane >> 2);
#pragma unroll
        for (int hf = 0; hf < 2; hf++) {
            int o = mtile*128 + r0 + hf*8;
            float sc = __ldg(g2 + o) * rsqrtf(__ldg(v2 + o) + EPSV);
            float bb = (__ldg(b2 + o) - __ldg(m2 + o)) * sc + __ldg(be2 + o);
            float* op = out + ((size_t)n*CCH + o)*TT*HW + pbase + wn*64 + (lane & 3)*2;
#pragma unroll
            for (int nt = 0; nt < 8; nt++) {
                float2 v;
                v.x = fmaxf(acc[mt][nt][hf*2 + 0]*sc + bb, 0.f);
                v.y = fmaxf(acc[mt][nt][hf*2 + 1]*sc + bb, 0.f);
                *(float2*)(op + nt*8) = v;
            }
        }
    }
#undef ISSUE
}

extern "C" void kernel_launch(void* const* d_in, const int* in_sizes, int n_in,
                              void* d_out, int out_size)
{
    (void)in_sizes; (void)n_in; (void)out_size;
    const float* x   = (const float*)d_in[0];
    const float* w1  = (const float*)d_in[1];
    const float* b1  = (const float*)d_in[2];
    const float* g1  = (const float*)d_in[3];
    const float* be1 = (const float*)d_in[4];
    const float* m1  = (const float*)d_in[5];
    const float* v1  = (const float*)d_in[6];
    const float* wp  = (const float*)d_in[7];
    const float* bp  = (const float*)d_in[8];
    const float* wq  = (const float*)d_in[9];
    const float* bq  = (const float*)d_in[10];
    const float* wt  = (const float*)d_in[11];
    const float* bt  = (const float*)d_in[12];
    const float* w2  = (const float*)d_in[13];
    const float* b2  = (const float*)d_in[14];
    const float* g2  = (const float*)d_in[15];
    const float* be2 = (const float*)d_in[16];
    const float* m2  = (const float*)d_in[17];
    const float* v2  = (const float*)d_in[18];
    float* out = (float*)d_out;

    const int kA_smem = (4096 + 16384) * 4;          // 80 KB
    cudaFuncSetAttribute(kA, cudaFuncAttributeMaxDynamicSharedMemorySize, kA_smem);

    kA<<<256, 512, kA_smem>>>(x, w1, b1, g1, be1, m1, v1, w2);
    kB<<<8, 256>>>(wp, bp, wq, bq, wt, bt);
    kC<<<NB*256*4, 256>>>(x);
    kD<<<2048, 256>>>(b2, g2, be2, m2, v2, out);
}